// round 16
// baseline (speedup 1.0000x reference)
#include <cuda_runtime.h>
#include <cuda_bf16.h>
#include <cstdint>

#define DEV_INLINE __device__ __forceinline__

constexpr int N_PTS = 131072;
constexpr int K_CL  = 256;
constexpr int D_DIM = 32;
constexpr int NCH   = 18;     // 16 circular-pair chunks + 2 tail chunks

// ---------------- device-global scratch ----------------
// U in MMA-fragment-major layout: [chunk][n-tile 0..31][lane 0..31] x uint4
__device__ __align__(128) uint32_t U_lg[NCH * 32 * 32 * 4];
__device__ float g_g[K_CL];           // g'_k = log|w_k| + 0.5 logdet(A_k) - 0.5 c^T A c
__device__ float C_g, LW_g;           // max g', log sum|w|
__device__ float part_g[2 * N_PTS];   // per-half partial exp-sums

// ---------------- helpers ----------------
DEV_INLINE uint32_t mulb2(uint32_t a, uint32_t b) {
    uint32_t d; asm("mul.rn.bf16x2 %0,%1,%2;" : "=r"(d) : "r"(a), "r"(b)); return d;
}
DEV_INLINE uint32_t prmt5432(uint32_t a, uint32_t b) {
    uint32_t d; asm("prmt.b32 %0,%1,%2,0x5432;" : "=r"(d) : "r"(a), "r"(b)); return d;
}
DEV_INLINE void mma16816(float* c, const uint32_t* a, uint32_t b0, uint32_t b1) {
    asm volatile(
        "mma.sync.aligned.m16n8k16.row.col.f32.bf16.bf16.f32 "
        "{%0,%1,%2,%3}, {%4,%5,%6,%7}, {%8,%9}, {%0,%1,%2,%3};"
        : "+f"(c[0]), "+f"(c[1]), "+f"(c[2]), "+f"(c[3])
        : "r"(a[0]), "r"(a[1]), "r"(a[2]), "r"(a[3]), "r"(b0), "r"(b1));
}

// ---------------- per-cluster prep ----------------
// kslot = 2q + r + 8m  <->  logical d = 8q + 2m + r
__global__ void k_prep(const float* __restrict__ centers,
                       const float* __restrict__ S,
                       const float* __restrict__ w) {
    __shared__ float Ssh[D_DIM * D_DIM];
    __shared__ float Ash[D_DIM * 33];
    __shared__ float csh[D_DIM];
    __shared__ float msh[D_DIM];
    int k = blockIdx.x, t = threadIdx.x;

    #pragma unroll
    for (int qq = 0; qq < 4; qq++) Ssh[t + 256 * qq] = S[k * 1024 + t + 256 * qq];
    if (t < 32) csh[t] = centers[k * 32 + t];
    __syncthreads();

    #pragma unroll
    for (int qq = 0; qq < 4; qq++) {
        int idx = t + 256 * qq;
        int d = idx >> 5, f = idx & 31;
        float a = 0.f;
        #pragma unroll
        for (int e = 0; e < 32; e++) a += Ssh[d * 32 + e] * Ssh[f * 32 + e];
        Ash[d * 33 + f] = a;
    }
    __syncthreads();

    if (t < 32) {
        float m = 0.f;
        #pragma unroll
        for (int f = 0; f < 32; f++) m += Ash[t * 33 + f] * csh[f];
        msh[t] = m;
    }
    __syncthreads();

    // write U fragment-major: 18 chunks x 16 u32 per cluster = 288 u32
    for (int p = t; p < 288; p += 256) {
        int c = p >> 4, q = (p >> 2) & 3, m = p & 3;
        float v[2];
        #pragma unroll
        for (int r = 0; r < 2; r++) {
            int d = 8 * q + 2 * m + r;
            float val;
            if (c == 0)       val = -0.5f * Ash[d * 33 + d];
            else if (c < 16)  val = -Ash[d * 33 + ((d + c) & 31)];
            else if (c == 16) val = (q < 2) ? -Ash[d * 33 + d + 16] : msh[d - 16];
            else              val = (q < 2) ? msh[d + 16] : 0.f;
            v[r] = val;
        }
        __nv_bfloat162 b2 = __floats2bfloat162_rn(v[0], v[1]);
        U_lg[(((c * 32) + (k >> 3)) * 32 + (k & 7) * 4 + q) * 4 + m] = *(uint32_t*)&b2;
    }
    __syncthreads();

    if (t < 32) {
        float cAc = msh[t] * csh[t];
        #pragma unroll
        for (int o = 16; o > 0; o >>= 1) cAc += __shfl_xor_sync(0xffffffff, cAc, o);

        // log|det S| via register-resident unpivoted Gaussian elimination:
        // 0.5 logdet(A) = 0.5 logdet(S S^T) = log|det S|; lane c holds column c.
        float v[32];
        #pragma unroll
        for (int r = 0; r < 32; r++) v[r] = Ssh[r * 32 + t];
        float det = 1.f;
        #pragma unroll
        for (int j = 0; j < 32; j++) {
            float p = __shfl_sync(0xffffffffu, v[j], j);   // pivot S[j][j]
            det *= p;
            float invp = __fdividef(1.f, p);
            #pragma unroll
            for (int r = j + 1; r < 32; r++) {
                float f = __shfl_sync(0xffffffffu, v[r], j) * invp;
                v[r] -= f * v[j];
            }
        }
        float halflogdet = logf(fmaxf(fabsf(det), 1e-35f));

        if (t == 0)
            g_g[k] = logf(fabsf(w[k]) + 1e-37f) + halflogdet - 0.5f * cAc;
    }
}

__global__ void k_stats(const float* __restrict__ w) {
    __shared__ float sm[256], sw[256];
    int t = threadIdx.x;
    sm[t] = g_g[t];
    sw[t] = fabsf(w[t]);
    __syncthreads();
    for (int s = 128; s > 0; s >>= 1) {
        if (t < s) { sm[t] = fmaxf(sm[t], sm[t + s]); sw[t] += sw[t + s]; }
        __syncthreads();
    }
    if (t == 0) { C_g = sm[0]; LW_g = logf(sw[0] + 1e-30f); }
}

// ---------------- main: register-resident F, direct-LDG B, syncless mainloop ----------------
// grid = 2048: blockIdx>>1 = point tile (128 pts), blockIdx&1 = cluster half (128 n)
__global__ __launch_bounds__(512, 1)
void k_main(const float* __restrict__ points) {
    __shared__ float part[512];
    int tid = threadIdx.x, wid = tid >> 5, lane = tid & 31;
    int g = lane >> 2, q = lane & 3;
    int warp_r = wid >> 2, warp_c = wid & 3;
    int khalf = blockIdx.x & 1;
    int i0 = (blockIdx.x >> 1) * 128;

    // xself / xrot: 4 rows x 4 bf16x2 (x[8q .. 8q+7] per row), register-resident
    uint32_t xs[4][4], xr[4][4];
    #pragma unroll
    for (int j = 0; j < 4; j++) {
        int R = warp_r * 32 + (j >> 1) * 16 + (j & 1) * 8 + g;
        const float4* pp = (const float4*)(points + (size_t)(i0 + R) * 32 + q * 8);
        float4 f0 = __ldg(pp), f1 = __ldg(pp + 1);
        __nv_bfloat162 b;
        b = __floats2bfloat162_rn(f0.x, f0.y); xs[j][0] = *(uint32_t*)&b;
        b = __floats2bfloat162_rn(f0.z, f0.w); xs[j][1] = *(uint32_t*)&b;
        b = __floats2bfloat162_rn(f1.x, f1.y); xs[j][2] = *(uint32_t*)&b;
        b = __floats2bfloat162_rn(f1.z, f1.w); xs[j][3] = *(uint32_t*)&b;
        #pragma unroll
        for (int m = 0; m < 4; m++) xr[j][m] = xs[j][m];
    }

    // B pointer (uint4 units): tile stride 32, chunk stride 32*32
    const uint4* ub = ((const uint4*)U_lg) + (size_t)(khalf * 16 + warp_c * 4) * 32 + lane;
    uint4 rb[4];
    #pragma unroll
    for (int t = 0; t < 4; t++) rb[t] = __ldg(ub + t * 32);

    float acc[2][4][4];
    #pragma unroll
    for (int a = 0; a < 2; a++)
        #pragma unroll
        for (int b = 0; b < 4; b++)
            #pragma unroll
            for (int j = 0; j < 4; j++) acc[a][b][j] = 0.f;

    int srcl = (lane & ~3) | ((q + 1) & 3);

    // k-step-major MMA order: all 8 MMAs of ks0 (8 distinct accs), then ks1.
    // Accumulator reuse distance = 8 MMAs -> HMMA latency fully covered.
    #define DO_CHUNK(prod, c) do {                                               \
        uint4 b0 = rb[0], b1 = rb[1], b2 = rb[2], b3 = rb[3];                     \
        if ((c) + 1 < NCH) {                                                      \
            rb[0] = __ldg(ub + (((c) + 1) * 32 + 0) * 32);                        \
            rb[1] = __ldg(ub + (((c) + 1) * 32 + 1) * 32);                        \
            rb[2] = __ldg(ub + (((c) + 1) * 32 + 2) * 32);                        \
            rb[3] = __ldg(ub + (((c) + 1) * 32 + 3) * 32);                        \
        }                                                                         \
        {   /* k-step 0 */                                                        \
            uint32_t A0[4] = {prod[0][0], prod[1][0], prod[0][1], prod[1][1]};    \
            uint32_t A1[4] = {prod[2][0], prod[3][0], prod[2][1], prod[3][1]};    \
            mma16816(acc[0][0], A0, b0.x, b0.y);                                  \
            mma16816(acc[1][0], A1, b0.x, b0.y);                                  \
            mma16816(acc[0][1], A0, b1.x, b1.y);                                  \
            mma16816(acc[1][1], A1, b1.x, b1.y);                                  \
            mma16816(acc[0][2], A0, b2.x, b2.y);                                  \
            mma16816(acc[1][2], A1, b2.x, b2.y);                                  \
            mma16816(acc[0][3], A0, b3.x, b3.y);                                  \
            mma16816(acc[1][3], A1, b3.x, b3.y);                                  \
        }                                                                         \
        {   /* k-step 1 */                                                        \
            uint32_t A0[4] = {prod[0][2], prod[1][2], prod[0][3], prod[1][3]};    \
            uint32_t A1[4] = {prod[2][2], prod[3][2], prod[2][3], prod[3][3]};    \
            mma16816(acc[0][0], A0, b0.z, b0.w);                                  \
            mma16816(acc[1][0], A1, b0.z, b0.w);                                  \
            mma16816(acc[0][1], A0, b1.z, b1.w);                                  \
            mma16816(acc[1][1], A1, b1.z, b1.w);                                  \
            mma16816(acc[0][2], A0, b2.z, b2.w);                                  \
            mma16816(acc[1][2], A1, b2.z, b2.w);                                  \
            mma16816(acc[0][3], A0, b3.z, b3.w);                                  \
            mma16816(acc[1][3], A1, b3.z, b3.w);                                  \
        }                                                                         \
    } while (0)

    for (int c = 0; c < 16; c++) {
        uint32_t prod[4][4];
        #pragma unroll
        for (int j = 0; j < 4; j++)
            #pragma unroll
            for (int m = 0; m < 4; m++) prod[j][m] = mulb2(xs[j][m], xr[j][m]);
        // rotate xrot by one element BEFORE the MMA burst (independent work pads issue)
        #pragma unroll
        for (int j = 0; j < 4; j++) {
            uint32_t inc = __shfl_sync(0xffffffffu, xr[j][0], srcl);
            xr[j][0] = prmt5432(xr[j][0], xr[j][1]);
            xr[j][1] = prmt5432(xr[j][1], xr[j][2]);
            xr[j][2] = prmt5432(xr[j][2], xr[j][3]);
            xr[j][3] = prmt5432(xr[j][3], inc);
        }
        DO_CHUNK(prod, c);
    }
    {   // chunk 16: q<2: pairs (d, d+16); q>=2: linear x_{d-16} (times m in U)
        uint32_t prod[4][4];
        #pragma unroll
        for (int j = 0; j < 4; j++)
            #pragma unroll
            for (int m = 0; m < 4; m++)
                prod[j][m] = (q < 2) ? mulb2(xs[j][m], xr[j][m]) : xr[j][m];
        DO_CHUNK(prod, 16);
    }
    {   // chunk 17: q<2: linear x_{d+16}; q>=2: zero
        uint32_t prod[4][4];
        #pragma unroll
        for (int j = 0; j < 4; j++)
            #pragma unroll
            for (int m = 0; m < 4; m++)
                prod[j][m] = (q < 2) ? xr[j][m] : 0u;
        DO_CHUNK(prod, 17);
    }
    #undef DO_CHUNK

    // -------- epilogue: exp-sum over this half's 128 clusters --------
    float C = C_g;
    int n0 = khalf * 128 + warp_c * 32;
    float g0[4], g1[4];
    #pragma unroll
    for (int t = 0; t < 4; t++) {
        g0[t] = g_g[n0 + t * 8 + q * 2]     - C;
        g1[t] = g_g[n0 + t * 8 + q * 2 + 1] - C;
    }
    #pragma unroll
    for (int rt = 0; rt < 2; rt++)
        #pragma unroll
        for (int h = 0; h < 2; h++) {
            float e = 0.f;
            #pragma unroll
            for (int t = 0; t < 4; t++) {
                e += __expf(acc[rt][t][2 * h]     + g0[t]);
                e += __expf(acc[rt][t][2 * h + 1] + g1[t]);
            }
            e += __shfl_xor_sync(0xffffffffu, e, 1);
            e += __shfl_xor_sync(0xffffffffu, e, 2);
            if (q == 0)
                part[(warp_r * 32 + rt * 16 + h * 8 + g) * 4 + warp_c] = e;
        }
    __syncthreads();
    if (tid < 128) {
        float s = part[tid * 4] + part[tid * 4 + 1] + part[tid * 4 + 2] + part[tid * 4 + 3];
        part_g[(size_t)khalf * N_PTS + i0 + tid] = s;
    }
}

__global__ void k_combine(const float* __restrict__ thr, float* __restrict__ out) {
    int i = blockIdx.x * 256 + threadIdx.x;
    out[i] = logf(part_g[i] + part_g[N_PTS + i]) + C_g - LW_g - thr[0];
}

// ---------------- launch ----------------
extern "C" void kernel_launch(void* const* d_in, const int* in_sizes, int n_in,
                              void* d_out, int out_size) {
    const float* points  = (const float*)d_in[0];
    const float* centers = (const float*)d_in[1];
    const float* covs    = (const float*)d_in[2];
    const float* weights = (const float*)d_in[3];
    const float* thresh  = (const float*)d_in[4];
    float* out = (float*)d_out;

    int n = in_sizes[0] / D_DIM;     // 131072

    k_prep<<<K_CL, 256>>>(centers, covs, weights);
    k_stats<<<1, 256>>>(weights);
    k_main<<<(n / 128) * 2, 512>>>(points);
    k_combine<<<n / 256, 256>>>(thresh, out);
}

// round 17
// speedup vs baseline: 1.1619x; 1.1619x over previous
#include <cuda_runtime.h>
#include <cuda_bf16.h>
#include <cstdint>

#define DEV_INLINE __device__ __forceinline__

constexpr int N_PTS = 131072;
constexpr int K_CL  = 256;
constexpr int D_DIM = 32;
constexpr int NCH   = 18;     // 16 circular-pair chunks + 2 tail chunks

// ---------------- device-global scratch ----------------
// U in MMA-fragment-major layout: [chunk][n-tile 0..31][lane 0..31] x uint4
__device__ __align__(128) uint32_t U_lg[NCH * 32 * 32 * 4];
__device__ float g_g[K_CL];           // g'_k = log|w_k| + 0.5 logdet(A_k) - 0.5 c^T A c
__device__ float C_g, LW_g;           // max g', log sum|w|
__device__ float part_g[4 * N_PTS];   // per-quarter partial exp-sums

// ---------------- helpers ----------------
DEV_INLINE uint32_t mulb2(uint32_t a, uint32_t b) {
    uint32_t d; asm("mul.rn.bf16x2 %0,%1,%2;" : "=r"(d) : "r"(a), "r"(b)); return d;
}
DEV_INLINE uint32_t prmt5432(uint32_t a, uint32_t b) {
    uint32_t d; asm("prmt.b32 %0,%1,%2,0x5432;" : "=r"(d) : "r"(a), "r"(b)); return d;
}
DEV_INLINE void mma16816(float* c, const uint32_t* a, uint32_t b0, uint32_t b1) {
    asm volatile(
        "mma.sync.aligned.m16n8k16.row.col.f32.bf16.bf16.f32 "
        "{%0,%1,%2,%3}, {%4,%5,%6,%7}, {%8,%9}, {%0,%1,%2,%3};"
        : "+f"(c[0]), "+f"(c[1]), "+f"(c[2]), "+f"(c[3])
        : "r"(a[0]), "r"(a[1]), "r"(a[2]), "r"(a[3]), "r"(b0), "r"(b1));
}

// ---------------- per-cluster prep ----------------
// kslot = 2q + r + 8m  <->  logical d = 8q + 2m + r
__global__ void k_prep(const float* __restrict__ centers,
                       const float* __restrict__ S,
                       const float* __restrict__ w) {
    __shared__ float Ssh[D_DIM * D_DIM];
    __shared__ float Ash[D_DIM * 33];
    __shared__ float csh[D_DIM];
    __shared__ float msh[D_DIM];
    int k = blockIdx.x, t = threadIdx.x;

    #pragma unroll
    for (int qq = 0; qq < 4; qq++) Ssh[t + 256 * qq] = S[k * 1024 + t + 256 * qq];
    if (t < 32) csh[t] = centers[k * 32 + t];
    __syncthreads();

    #pragma unroll
    for (int qq = 0; qq < 4; qq++) {
        int idx = t + 256 * qq;
        int d = idx >> 5, f = idx & 31;
        float a = 0.f;
        #pragma unroll
        for (int e = 0; e < 32; e++) a += Ssh[d * 32 + e] * Ssh[f * 32 + e];
        Ash[d * 33 + f] = a;
    }
    __syncthreads();

    if (t < 32) {
        float m = 0.f;
        #pragma unroll
        for (int f = 0; f < 32; f++) m += Ash[t * 33 + f] * csh[f];
        msh[t] = m;
    }
    __syncthreads();

    // write U fragment-major: 18 chunks x 16 u32 per cluster = 288 u32
    for (int p = t; p < 288; p += 256) {
        int c = p >> 4, q = (p >> 2) & 3, m = p & 3;
        float v[2];
        #pragma unroll
        for (int r = 0; r < 2; r++) {
            int d = 8 * q + 2 * m + r;
            float val;
            if (c == 0)       val = -0.5f * Ash[d * 33 + d];
            else if (c < 16)  val = -Ash[d * 33 + ((d + c) & 31)];
            else if (c == 16) val = (q < 2) ? -Ash[d * 33 + d + 16] : msh[d - 16];
            else              val = (q < 2) ? msh[d + 16] : 0.f;
            v[r] = val;
        }
        __nv_bfloat162 b2 = __floats2bfloat162_rn(v[0], v[1]);
        U_lg[(((c * 32) + (k >> 3)) * 32 + (k & 7) * 4 + q) * 4 + m] = *(uint32_t*)&b2;
    }
    __syncthreads();

    if (t < 32) {
        float cAc = msh[t] * csh[t];
        #pragma unroll
        for (int o = 16; o > 0; o >>= 1) cAc += __shfl_xor_sync(0xffffffff, cAc, o);

        // log|det S| via register-resident unpivoted Gaussian elimination:
        // 0.5 logdet(A) = 0.5 logdet(S S^T) = log|det S|; lane c holds column c.
        float v[32];
        #pragma unroll
        for (int r = 0; r < 32; r++) v[r] = Ssh[r * 32 + t];
        float det = 1.f;
        #pragma unroll
        for (int j = 0; j < 32; j++) {
            float p = __shfl_sync(0xffffffffu, v[j], j);   // pivot S[j][j]
            det *= p;
            float invp = __fdividef(1.f, p);
            #pragma unroll
            for (int r = j + 1; r < 32; r++) {
                float f = __shfl_sync(0xffffffffu, v[r], j) * invp;
                v[r] -= f * v[j];
            }
        }
        float halflogdet = logf(fmaxf(fabsf(det), 1e-35f));

        if (t == 0)
            g_g[k] = logf(fabsf(w[k]) + 1e-37f) + halflogdet - 0.5f * cAc;
    }
}

__global__ void k_stats(const float* __restrict__ w) {
    __shared__ float sm[256], sw[256];
    int t = threadIdx.x;
    sm[t] = g_g[t];
    sw[t] = fabsf(w[t]);
    __syncthreads();
    for (int s = 128; s > 0; s >>= 1) {
        if (t < s) { sm[t] = fmaxf(sm[t], sm[t + s]); sw[t] += sw[t + s]; }
        __syncthreads();
    }
    if (t == 0) { C_g = sm[0]; LW_g = logf(sw[0] + 1e-30f); }
}

// ---------------- main: 256-thread CTAs, 2 per SM; M128 x N64 per CTA ----------------
// grid = 4096: blockIdx>>2 = point tile (128 pts), blockIdx&3 = cluster quarter (64 n)
// 8 warps as 4x2: warp_r rows 32*warp_r.. (+32), warp_c cols 32*warp_c within quarter.
__global__ __launch_bounds__(256, 2)
void k_main(const float* __restrict__ points) {
    __shared__ float part[256];
    int tid = threadIdx.x, wid = tid >> 5, lane = tid & 31;
    int g = lane >> 2, q = lane & 3;
    int warp_r = wid >> 1, warp_c = wid & 1;
    int kq = blockIdx.x & 3;
    int i0 = (blockIdx.x >> 2) * 128;

    // xself / xrot: 4 rows x 4 bf16x2 (x[8q .. 8q+7] per row), register-resident
    uint32_t xs[4][4], xr[4][4];
    #pragma unroll
    for (int j = 0; j < 4; j++) {
        int R = warp_r * 32 + (j >> 1) * 16 + (j & 1) * 8 + g;
        const float4* pp = (const float4*)(points + (size_t)(i0 + R) * 32 + q * 8);
        float4 f0 = __ldg(pp), f1 = __ldg(pp + 1);
        __nv_bfloat162 b;
        b = __floats2bfloat162_rn(f0.x, f0.y); xs[j][0] = *(uint32_t*)&b;
        b = __floats2bfloat162_rn(f0.z, f0.w); xs[j][1] = *(uint32_t*)&b;
        b = __floats2bfloat162_rn(f1.x, f1.y); xs[j][2] = *(uint32_t*)&b;
        b = __floats2bfloat162_rn(f1.z, f1.w); xs[j][3] = *(uint32_t*)&b;
        #pragma unroll
        for (int m = 0; m < 4; m++) xr[j][m] = xs[j][m];
    }

    // B pointer (uint4 units): tile stride 32, chunk stride 32*32
    const uint4* ub = ((const uint4*)U_lg) + (size_t)(kq * 8 + warp_c * 4) * 32 + lane;
    uint4 rb[4];
    #pragma unroll
    for (int t = 0; t < 4; t++) rb[t] = __ldg(ub + t * 32);

    float acc[2][4][4];
    #pragma unroll
    for (int a = 0; a < 2; a++)
        #pragma unroll
        for (int b = 0; b < 4; b++)
            #pragma unroll
            for (int j = 0; j < 4; j++) acc[a][b][j] = 0.f;

    int srcl = (lane & ~3) | ((q + 1) & 3);

    #define DO_CHUNK(prod, c) do {                                              \
        _Pragma("unroll")                                                        \
        for (int t = 0; t < 4; t++) {                                            \
            uint4 b = rb[t];                                                     \
            if ((c) + 1 < NCH) rb[t] = __ldg(ub + (((c) + 1) * 32 + t) * 32);    \
            { uint32_t A[4] = {prod[0][0], prod[1][0], prod[0][1], prod[1][1]};  \
              mma16816(acc[0][t], A, b.x, b.y); }                                \
            { uint32_t A[4] = {prod[0][2], prod[1][2], prod[0][3], prod[1][3]};  \
              mma16816(acc[0][t], A, b.z, b.w); }                                \
            { uint32_t A[4] = {prod[2][0], prod[3][0], prod[2][1], prod[3][1]};  \
              mma16816(acc[1][t], A, b.x, b.y); }                                \
            { uint32_t A[4] = {prod[2][2], prod[3][2], prod[2][3], prod[3][3]};  \
              mma16816(acc[1][t], A, b.z, b.w); }                                \
        }                                                                        \
    } while (0)

    for (int c = 0; c < 16; c++) {
        uint32_t prod[4][4];
        #pragma unroll
        for (int j = 0; j < 4; j++)
            #pragma unroll
            for (int m = 0; m < 4; m++) prod[j][m] = mulb2(xs[j][m], xr[j][m]);
        DO_CHUNK(prod, c);
        // rotate xrot by one element (distributed across q-lanes)
        #pragma unroll
        for (int j = 0; j < 4; j++) {
            uint32_t inc = __shfl_sync(0xffffffffu, xr[j][0], srcl);
            xr[j][0] = prmt5432(xr[j][0], xr[j][1]);
            xr[j][1] = prmt5432(xr[j][1], xr[j][2]);
            xr[j][2] = prmt5432(xr[j][2], xr[j][3]);
            xr[j][3] = prmt5432(xr[j][3], inc);
        }
    }
    {   // chunk 16: q<2: pairs (d, d+16); q>=2: linear x_{d-16} (times m in U)
        uint32_t prod[4][4];
        #pragma unroll
        for (int j = 0; j < 4; j++)
            #pragma unroll
            for (int m = 0; m < 4; m++)
                prod[j][m] = (q < 2) ? mulb2(xs[j][m], xr[j][m]) : xr[j][m];
        DO_CHUNK(prod, 16);
    }
    {   // chunk 17: q<2: linear x_{d+16}; q>=2: zero
        uint32_t prod[4][4];
        #pragma unroll
        for (int j = 0; j < 4; j++)
            #pragma unroll
            for (int m = 0; m < 4; m++)
                prod[j][m] = (q < 2) ? xr[j][m] : 0u;
        DO_CHUNK(prod, 17);
    }
    #undef DO_CHUNK

    // -------- epilogue: exp-sum over this quarter's 64 clusters --------
    float C = C_g;
    int n0 = kq * 64 + warp_c * 32;
    float g0[4], g1[4];
    #pragma unroll
    for (int t = 0; t < 4; t++) {
        g0[t] = g_g[n0 + t * 8 + q * 2]     - C;
        g1[t] = g_g[n0 + t * 8 + q * 2 + 1] - C;
    }
    #pragma unroll
    for (int rt = 0; rt < 2; rt++)
        #pragma unroll
        for (int h = 0; h < 2; h++) {
            float e = 0.f;
            #pragma unroll
            for (int t = 0; t < 4; t++) {
                e += __expf(acc[rt][t][2 * h]     + g0[t]);
                e += __expf(acc[rt][t][2 * h + 1] + g1[t]);
            }
            e += __shfl_xor_sync(0xffffffffu, e, 1);
            e += __shfl_xor_sync(0xffffffffu, e, 2);
            if (q == 0)
                part[(warp_r * 32 + rt * 16 + h * 8 + g) * 2 + warp_c] = e;
        }
    __syncthreads();
    if (tid < 128) {
        float s = part[tid * 2] + part[tid * 2 + 1];
        part_g[(size_t)kq * N_PTS + i0 + tid] = s;
    }
}

__global__ void k_combine(const float* __restrict__ thr, float* __restrict__ out) {
    int i = blockIdx.x * 256 + threadIdx.x;
    float s = part_g[i] + part_g[N_PTS + i] + part_g[2 * N_PTS + i] + part_g[3 * N_PTS + i];
    out[i] = logf(s) + C_g - LW_g - thr[0];
}

// ---------------- launch ----------------
extern "C" void kernel_launch(void* const* d_in, const int* in_sizes, int n_in,
                              void* d_out, int out_size) {
    const float* points  = (const float*)d_in[0];
    const float* centers = (const float*)d_in[1];
    const float* covs    = (const float*)d_in[2];
    const float* weights = (const float*)d_in[3];
    const float* thresh  = (const float*)d_in[4];
    float* out = (float*)d_out;

    int n = in_sizes[0] / D_DIM;     // 131072

    k_prep<<<K_CL, 256>>>(centers, covs, weights);
    k_stats<<<1, 256>>>(weights);
    k_main<<<(n / 128) * 4, 256>>>(points);
    k_combine<<<n / 256, 256>>>(thresh, out);
}